// round 16
// baseline (speedup 1.0000x reference)
#include <cuda_runtime.h>
#include <math_constants.h>

#define NST 1024
#define TT  4096
#define DD  20

// ---------------- device scratch (no allocations allowed) ----------------
__device__ float g_LT[NST * NST];         // 4 MB  log(transition), row-major [k][j]
__device__ float g_rowmax[NST];
__device__ float g_rowmin[NST];
__device__ float g_M[DD * NST];           // mean          (layout [d][n])
__device__ float g_S[DD * NST];           // 2*s^2         (layout [d][n])
__device__ float g_C[DD * NST];           // (2*pi*s)^-0.5 (layout [d][n])
__device__ float g_E[TT * NST];           // 16 MB emissions E[t][n] (may be -inf)
__device__ unsigned short g_bp[TT * NST]; // 8 MB backpointers, rows t=1..T-1
__device__ int g_last;

// ---------------- K1a: log-transition + per-row min/max ----------------
__global__ void k_lt(const float* __restrict__ trans) {
    int k = blockIdx.x;
    int tid = threadIdx.x;
    float mx = -CUDART_INF_F, mn = CUDART_INF_F;
    for (int j = tid; j < NST; j += 256) {
        float v = logf(trans[k * NST + j]);
        g_LT[k * NST + j] = v;
        mx = fmaxf(mx, v);
        mn = fminf(mn, v);
    }
    for (int o = 16; o; o >>= 1) {
        mx = fmaxf(mx, __shfl_xor_sync(0xffffffffu, mx, o));
        mn = fminf(mn, __shfl_xor_sync(0xffffffffu, mn, o));
    }
    __shared__ float smx[8], smn[8];
    if ((tid & 31) == 0) { smx[tid >> 5] = mx; smn[tid >> 5] = mn; }
    __syncthreads();
    if (tid == 0) {
        for (int w = 1; w < 8; w++) { mx = fmaxf(mx, smx[w]); mn = fminf(mn, smn[w]); }
        g_rowmax[k] = mx;
        g_rowmin[k] = mn;
    }
}

// ---------------- K1b: emission parameter prep ----------------
__global__ void k_params(const float* __restrict__ ep) {
    int n = blockIdx.x;
    int d = threadIdx.x;  // 32 threads, d < 20 active
    if (d < DD) {
        float m = ep[(n * DD + d) * 2 + 0];
        float s = ep[(n * DD + d) * 2 + 1];
        g_M[d * NST + n] = m;
        g_S[d * NST + n] = 2.0f * (s * s);                       // 2*std^2
        g_C[d * NST + n] = 1.0f / sqrtf(2.0f * CUDART_PI_F * s); // (2*pi*std)^-0.5
    }
}

// ---------------- K2: emissions, exact reference form (PROVEN rel_err=0) ----------------
__global__ void __launch_bounds__(256) k_emis(const float* __restrict__ ev) {
    int n = blockIdx.y * 256 + threadIdx.x;
    int t0 = blockIdx.x * 64;
    __shared__ float sx[64][DD];
    for (int i = threadIdx.x; i < 64 * DD; i += 256) {
        int tt = i / DD, dd = i % DD;
        sx[tt][dd] = ev[(t0 + tt) * DD + dd];
    }
    __syncthreads();
    float M[DD], S[DD], C[DD];
#pragma unroll
    for (int d = 0; d < DD; d++) {
        M[d] = g_M[d * NST + n];
        S[d] = g_S[d * NST + n];
        C[d] = g_C[d * NST + n];
    }
    for (int tt = 0; tt < 64; tt++) {
        float acc = 0.f;
#pragma unroll
        for (int d = 0; d < DD; d++) {
            float diff = sx[tt][d] - M[d];
            float p = C[d] * expf(-(diff * diff) / S[d]);
            acc += logf(p);                 // -inf kept, like reference
        }
        g_E[(t0 + tt) * NST + n] = acc;
    }
}

// ---------------- K3: pruned Viterbi forward, lean step (single CTA, 256 thr) ----------
// Thread u owns states/columns 4u..4u+3; prev column lives in registers (pv)
// with a shared float mirror for broadcast. Exact pruning as before:
// L = max_k(prev[k]+rowmin[k]); candidate iff prev[k]+rowmax[k] >= L.
// Candidate order is arbitrary: the scan carries an explicit (v, k) tie-break
// (v>b) || (v==b && k<a)  ==  jnp.argmax first-max semantics.
__global__ void __launch_bounds__(256, 1) k_viterbi(const float* __restrict__ prior) {
    __shared__ __align__(16) float spf[NST];   // prev column mirror
    __shared__ unsigned short cand[NST];       // per-warp sections of 128
    __shared__ int   s_cnt8[8];
    __shared__ float s_red[8];
    __shared__ float s_rv[8];
    __shared__ int   s_ri[8];

    int u = threadIdx.x;
    int wid = u >> 5, lane = u & 31;
    const unsigned FULL = 0xffffffffu;

    const float4* rmin4 = reinterpret_cast<const float4*>(g_rowmin);
    const float4* rmax4 = reinterpret_cast<const float4*>(g_rowmax);
    const float4* LT4 = reinterpret_cast<const float4*>(g_LT);
    float4 rmn = rmin4[u];
    float4 rmx = rmax4[u];

    // initial column: col0 = log(prior) + E[0]
    float4 pv;
    {
        const float4* pr4 = reinterpret_cast<const float4*>(prior);
        const float4* e4 = reinterpret_cast<const float4*>(g_E);
        float4 p = pr4[u];
        float4 e = e4[u];
        pv.x = logf(p.x) + e.x;
        pv.y = logf(p.y) + e.y;
        pv.z = logf(p.z) + e.z;
        pv.w = logf(p.w) + e.w;
    }
    float LT00 = g_LT[0];
    reinterpret_cast<float4*>(spf)[u] = pv;
    __syncthreads();

    for (int step = 1; step < TT; step++) {
        float4 e = *reinterpret_cast<const float4*>(g_E + step * NST + 4 * u);

        // ---- L = max_k (prev[k] + rowmin[k]) ----
        float sm = fmaxf(fmaxf(pv.x + rmn.x, pv.y + rmn.y),
                         fmaxf(pv.z + rmn.z, pv.w + rmn.w));
        for (int o = 16; o; o >>= 1) sm = fmaxf(sm, __shfl_xor_sync(FULL, sm, o));
        if (lane == 0) s_red[wid] = sm;
        __syncthreads();                                   // sync 1
        float L;
        {
            float v = s_red[lane & 7];
            v = fmaxf(v, __shfl_xor_sync(FULL, v, 1));
            v = fmaxf(v, __shfl_xor_sync(FULL, v, 2));
            v = fmaxf(v, __shfl_xor_sync(FULL, v, 4));
            L = v;                                         // all threads
        }

        // ---- candidate compaction into per-warp sections (order-free) ----
        bool p0 = (pv.x + rmx.x) >= L;
        bool p1 = (pv.y + rmx.y) >= L;
        bool p2 = (pv.z + rmx.z) >= L;
        bool p3 = (pv.w + rmx.w) >= L;
        unsigned m0 = __ballot_sync(FULL, p0);
        unsigned m1 = __ballot_sync(FULL, p1);
        unsigned m2 = __ballot_sync(FULL, p2);
        unsigned m3 = __ballot_sync(FULL, p3);
        unsigned lt = (1u << lane) - 1u;
        int c0 = __popc(m0), c01 = c0 + __popc(m1), c012 = c01 + __popc(m2);
        int base = wid << 7;
        if (p0) cand[base + __popc(m0 & lt)] = (unsigned short)(4 * u + 0);
        if (p1) cand[base + c0 + __popc(m1 & lt)] = (unsigned short)(4 * u + 1);
        if (p2) cand[base + c01 + __popc(m2 & lt)] = (unsigned short)(4 * u + 2);
        if (p3) cand[base + c012 + __popc(m3 & lt)] = (unsigned short)(4 * u + 3);
        if (lane == 0) s_cnt8[wid] = c012 + __popc(m3);
        __syncthreads();                                   // sync 2

        // ---- max-plus scan: every thread covers its 4 columns over ALL candidates ----
        float4 b = make_float4(-CUDART_INF_F, -CUDART_INF_F, -CUDART_INF_F, -CUDART_INF_F);
        int4 a = make_int4(0, 0, 0, 0);
        for (int w2 = 0; w2 < 8; w2++) {
            int cw = s_cnt8[w2];
            const unsigned short* cp = cand + (w2 << 7);
            for (int i = 0; i < cw; i++) {
                int k = cp[i];
                float pvk = spf[k];
                float4 f = LT4[k * (NST / 4) + u];
                float v0 = pvk + f.x;
                if (v0 > b.x || (v0 == b.x && k < a.x)) { b.x = v0; a.x = k; }
                float v1 = pvk + f.y;
                if (v1 > b.y || (v1 == b.y && k < a.y)) { b.y = v1; a.y = k; }
                float v2 = pvk + f.z;
                if (v2 > b.z || (v2 == b.z && k < a.z)) { b.z = v2; a.z = k; }
                float v3 = pvk + f.w;
                if (v3 > b.w || (v3 == b.w && k < a.w)) { b.w = v3; a.w = k; }
            }
        }
        // j==0 VALUE override (bp stays the generic argmax, matching backtrack)
        if (u == 0) b.x = pv.x + LT00;       // pv.x IS prev[0] for thread 0

        float4 nv = make_float4(b.x + e.x, b.y + e.y, b.z + e.z, b.w + e.w);
        ushort4 bpw = make_ushort4((unsigned short)a.x, (unsigned short)a.y,
                                   (unsigned short)a.z, (unsigned short)a.w);
        *reinterpret_cast<ushort4*>(g_bp + step * NST + 4 * u) = bpw;

        __syncthreads();                                   // sync 3 (spf reads done)
        pv = nv;
        reinterpret_cast<float4*>(spf)[u] = nv;
        // next iteration's sync 1 publishes spf before any cross-thread read
    }
    __syncthreads();

    // ---- final-column first-max argmax ----
    float bv = pv.x; int bi = 4 * u;
    if (pv.y > bv) { bv = pv.y; bi = 4 * u + 1; }
    if (pv.z > bv) { bv = pv.z; bi = 4 * u + 2; }
    if (pv.w > bv) { bv = pv.w; bi = 4 * u + 3; }
    for (int o = 16; o; o >>= 1) {
        float ov = __shfl_xor_sync(FULL, bv, o);
        int   oi = __shfl_xor_sync(FULL, bi, o);
        if (ov > bv || (ov == bv && oi < bi)) { bv = ov; bi = oi; }
    }
    if (lane == 0) { s_rv[wid] = bv; s_ri[wid] = bi; }
    __syncthreads();
    if (u == 0) {
        for (int w = 1; w < 8; w++)
            if (s_rv[w] > bv || (s_rv[w] == bv && s_ri[w] < bi)) { bv = s_rv[w]; bi = s_ri[w]; }
        g_last = bi;
    }
}

// ---------------- K4a: fill ENTIRE output buffer with `last` (float) ----------------
__global__ void k_fill(float* __restrict__ out, int n) {
    int last = g_last;
    for (int i = blockIdx.x * 256 + threadIdx.x; i < n; i += gridDim.x * 256)
        out[i] = (float)last;
}

// ---------------- K4b: serial backtrack, FLOAT output ----------------
// sequence = [s_0 .. s_{T-2}, last, last]
__global__ void k_backtrack(float* __restrict__ out) {
    int cur = g_last;
    out[TT] = (float)cur;
    out[TT - 1] = (float)cur;
    for (int i = TT - 2; i >= 0; i--) {
        cur = (int)g_bp[(i + 1) * NST + cur];
        out[i] = (float)cur;
    }
}

// ---------------- launch ----------------
extern "C" void kernel_launch(void* const* d_in, const int* in_sizes, int n_in,
                              void* d_out, int out_size) {
    // Bind inputs BY ELEMENT COUNT (all four counts distinct):
    //   evidence [T,D]=81920, prior [N]=1024, trans [N,N]=1048576, emission [N,D,2]=40960
    const float* evidence = 0;
    const float* prior = 0;
    const float* trans = 0;
    const float* emis = 0;
    for (int i = 0; i < n_in; i++) {
        switch (in_sizes[i]) {
            case TT * DD:       evidence = (const float*)d_in[i]; break;
            case NST:           prior    = (const float*)d_in[i]; break;
            case NST * NST:     trans    = (const float*)d_in[i]; break;
            case NST * DD * 2:  emis     = (const float*)d_in[i]; break;
        }
    }
    float* out = (float*)d_out;

    k_lt<<<NST, 256>>>(trans);
    k_params<<<NST, 32>>>(emis);
    k_emis<<<dim3(TT / 64, NST / 256), 256>>>(evidence);
    k_viterbi<<<1, 256>>>(prior);
    int n = out_size > 0 ? out_size : (TT + 1);
    int g = (n + 255) / 256; if (g > 64) g = 64;
    k_fill<<<g, 256>>>(out, n);
    k_backtrack<<<1, 1>>>(out);
}

// round 17
// speedup vs baseline: 2.8020x; 2.8020x over previous
#include <cuda_runtime.h>
#include <math_constants.h>
#include <cooperative_groups.h>

namespace cg = cooperative_groups;

#define NST 1024
#define TT  4096
#define DD  20
#define CSZ 8          // cluster size (CTAs)
#define CTHR 512       // threads per CTA
#define NCOL 128       // columns per CTA  (NST / CSZ)
#define NGRP 16        // candidate groups (= warps per CTA)

// ---------------- device scratch (no allocations allowed) ----------------
__device__ float g_LT[NST * NST];         // 4 MB  log(transition), row-major [k][j]
__device__ float g_rowmax[NST];
__device__ float g_rowmin[NST];
__device__ float g_M[DD * NST];           // mean          (layout [d][n])
__device__ float g_S[DD * NST];           // 2*s^2         (layout [d][n])
__device__ float g_C[DD * NST];           // (2*pi*s)^-0.5 (layout [d][n])
__device__ float g_E[TT * NST];           // 16 MB emissions E[t][n] (may be -inf)
__device__ unsigned short g_bp[TT * NST]; // 8 MB backpointers, rows t=1..T-1
__device__ int g_last;

// ---------------- K1a: log-transition + per-row min/max ----------------
__global__ void k_lt(const float* __restrict__ trans) {
    int k = blockIdx.x;
    int tid = threadIdx.x;
    float mx = -CUDART_INF_F, mn = CUDART_INF_F;
    for (int j = tid; j < NST; j += 256) {
        float v = logf(trans[k * NST + j]);
        g_LT[k * NST + j] = v;
        mx = fmaxf(mx, v);
        mn = fminf(mn, v);
    }
    for (int o = 16; o; o >>= 1) {
        mx = fmaxf(mx, __shfl_xor_sync(0xffffffffu, mx, o));
        mn = fminf(mn, __shfl_xor_sync(0xffffffffu, mn, o));
    }
    __shared__ float smx[8], smn[8];
    if ((tid & 31) == 0) { smx[tid >> 5] = mx; smn[tid >> 5] = mn; }
    __syncthreads();
    if (tid == 0) {
        for (int w = 1; w < 8; w++) { mx = fmaxf(mx, smx[w]); mn = fminf(mn, smn[w]); }
        g_rowmax[k] = mx;
        g_rowmin[k] = mn;
    }
}

// ---------------- K1b: emission parameter prep ----------------
__global__ void k_params(const float* __restrict__ ep) {
    int n = blockIdx.x;
    int d = threadIdx.x;  // 32 threads, d < 20 active
    if (d < DD) {
        float m = ep[(n * DD + d) * 2 + 0];
        float s = ep[(n * DD + d) * 2 + 1];
        g_M[d * NST + n] = m;
        g_S[d * NST + n] = 2.0f * (s * s);                       // 2*std^2
        g_C[d * NST + n] = 1.0f / sqrtf(2.0f * CUDART_PI_F * s); // (2*pi*std)^-0.5
    }
}

// ---------------- K2: emissions, exact reference form (PROVEN rel_err=0) ----------------
__global__ void __launch_bounds__(256) k_emis(const float* __restrict__ ev) {
    int n = blockIdx.y * 256 + threadIdx.x;
    int t0 = blockIdx.x * 64;
    __shared__ float sx[64][DD];
    for (int i = threadIdx.x; i < 64 * DD; i += 256) {
        int tt = i / DD, dd = i % DD;
        sx[tt][dd] = ev[(t0 + tt) * DD + dd];
    }
    __syncthreads();
    float M[DD], S[DD], C[DD];
#pragma unroll
    for (int d = 0; d < DD; d++) {
        M[d] = g_M[d * NST + n];
        S[d] = g_S[d * NST + n];
        C[d] = g_C[d * NST + n];
    }
    for (int tt = 0; tt < 64; tt++) {
        float acc = 0.f;
#pragma unroll
        for (int d = 0; d < DD; d++) {
            float diff = sx[tt][d] - M[d];
            float p = C[d] * expf(-(diff * diff) / S[d]);
            acc += logf(p);                 // -inf kept, like reference
        }
        g_E[(t0 + tt) * NST + n] = acc;
    }
}

// ---------------- K3: pruned Viterbi forward — 8-CTA cluster ----------------
// Each CTA mirrors the full prev column (double-buffered) and owns NCOL=128
// output columns. Exact pruning (identical in every CTA, so the candidate
// list needs no exchange): L = max_k(prev[k]+rowmin[k]); candidate iff
// prev[k]+rowmax[k] >= L. Compacted ASCENDING via cross-warp prefix =>
// strict > in the scan = jnp.argmax first-max; k-tie-break only in combines.
// Column leaders DSMEM-broadcast new values to all 8 mirrors; one
// cluster.sync per step.
__global__ void __launch_bounds__(CTHR, 1) __cluster_dims__(CSZ, 1, 1)
k_viterbi(const float* __restrict__ prior) {
    cg::cluster_group cluster = cg::this_cluster();
    unsigned r = cluster.block_rank();

    __shared__ __align__(16) float spf[2][NST];   // prev-column mirrors (ping-pong)
    __shared__ float srmn[NST], srmx[NST];
    __shared__ unsigned short cand[NST];
    __shared__ int   s_cnt[NGRP];
    __shared__ float s_red[NGRP];
    __shared__ float bests[NGRP][NCOL];
    __shared__ int   args[NGRP][NCOL];
    __shared__ float s_rv[NGRP];
    __shared__ int   s_ri[NGRP];

    const unsigned FULL = 0xffffffffu;
    int t = threadIdx.x;
    int wid = t >> 5, lane = t & 31;
    int q = wid;             // candidate group 0..15
    int u = t & 31;          // owns local columns 4u..4u+3
    int ccol = t >> 2;       // combine: local column 0..127
    int cpart = t & 3;       // combine: partial quarter 0..3

    // one-time setup
    for (int i = t; i < NST; i += CTHR) {
        srmn[i] = g_rowmin[i];
        srmx[i] = g_rowmax[i];
        spf[1][i] = logf(prior[i]) + g_E[i];     // col0 = log(prior)+E[0], read at step 1
    }
    float LT00 = g_LT[0];
    // generic pointers to every rank's spf base
    float* rp[CSZ];
#pragma unroll
    for (int rr = 0; rr < CSZ; rr++)
        rp[rr] = (float*)cluster.map_shared_rank((void*)&spf[0][0], rr);
    cluster.sync();

    const float4* LT4 = reinterpret_cast<const float4*>(g_LT);

    for (int step = 1; step < TT; step++) {
        int br = step & 1, bw = br ^ 1;
        const float* P = spf[br];
        float e = 0.f;
        if (cpart == 0) e = g_E[step * NST + (int)r * NCOL + ccol];  // leader prefetch

        // ---- A: L = max_k(prev[k] + rowmin[k]), 2 states/thread ----
        float a0 = P[2 * t] + srmn[2 * t];
        float a1 = P[2 * t + 1] + srmn[2 * t + 1];
        float sm = fmaxf(a0, a1);
        for (int o = 16; o; o >>= 1) sm = fmaxf(sm, __shfl_xor_sync(FULL, sm, o));
        if (lane == 0) s_red[wid] = sm;
        __syncthreads();                                  // bar1
        float L;
        {
            float v = (lane < NGRP) ? s_red[lane] : -CUDART_INF_F;
            v = fmaxf(v, __shfl_xor_sync(FULL, v, 1));
            v = fmaxf(v, __shfl_xor_sync(FULL, v, 2));
            v = fmaxf(v, __shfl_xor_sync(FULL, v, 4));
            v = fmaxf(v, __shfl_xor_sync(FULL, v, 8));
            L = __shfl_sync(FULL, v, 0);
        }

        // ---- B: candidate predicates + per-warp counts ----
        bool p0 = (P[2 * t] + srmx[2 * t]) >= L;
        bool p1 = (P[2 * t + 1] + srmx[2 * t + 1]) >= L;
        unsigned m0 = __ballot_sync(FULL, p0);
        unsigned m1 = __ballot_sync(FULL, p1);
        int cw = __popc(m0) + __popc(m1);
        if (lane == 0) s_cnt[wid] = cw;
        __syncthreads();                                  // bar2

        // cross-warp exclusive prefix (redundant in every thread, shfl scan)
        int C, base;
        {
            int x = (lane < NGRP) ? s_cnt[lane] : 0;
#pragma unroll
            for (int o = 1; o < NGRP; o <<= 1) {
                int y = __shfl_up_sync(FULL, x, o);
                if (lane >= o) x += y;
            }
            C = __shfl_sync(FULL, x, NGRP - 1);
            base = __shfl_sync(FULL, x, wid) - cw;        // exclusive prefix of this warp
        }
        unsigned ltm = (1u << lane) - 1u;
        int off = __popc(m0 & ltm) + __popc(m1 & ltm);
        if (p0) cand[base + off] = (unsigned short)(2 * t);
        if (p1) cand[base + off + (p0 ? 1 : 0)] = (unsigned short)(2 * t + 1);
        __syncthreads();                                  // bar3

        // ---- C: max-plus scan over this CTA's 128 columns ----
        float4 b = make_float4(-CUDART_INF_F, -CUDART_INF_F, -CUDART_INF_F, -CUDART_INF_F);
        int4 a = make_int4(0, 0, 0, 0);
        for (int c = q; c < C; c += NGRP) {
            int k = cand[c];
            float pvk = P[k];
            float4 f = LT4[k * (NST / 4) + (int)r * (NCOL / 4) + u];
            float v0 = pvk + f.x; if (v0 > b.x) { b.x = v0; a.x = k; }
            float v1 = pvk + f.y; if (v1 > b.y) { b.y = v1; a.y = k; }
            float v2 = pvk + f.z; if (v2 > b.z) { b.z = v2; a.z = k; }
            float v3 = pvk + f.w; if (v3 > b.w) { b.w = v3; a.w = k; }
        }
        bests[q][4 * u + 0] = b.x; args[q][4 * u + 0] = a.x;
        bests[q][4 * u + 1] = b.y; args[q][4 * u + 1] = a.y;
        bests[q][4 * u + 2] = b.z; args[q][4 * u + 2] = a.z;
        bests[q][4 * u + 3] = b.w; args[q][4 * u + 3] = a.w;
        __syncthreads();                                  // bar4

        // ---- D: combine 16 partials (4/thread, then quad shfl), k-tie-break ----
        float bv = -CUDART_INF_F; int ba = 0;
#pragma unroll
        for (int g2 = 0; g2 < 4; g2++) {
            int gi = cpart * 4 + g2;
            float v = bests[gi][ccol]; int aa = args[gi][ccol];
            if (v > bv || (v == bv && aa < ba)) { bv = v; ba = aa; }
        }
#pragma unroll
        for (int o = 1; o < 4; o <<= 1) {
            float ov = __shfl_xor_sync(FULL, bv, o);
            int   oa = __shfl_xor_sync(FULL, ba, o);
            if (ov > bv || (ov == bv && oa < ba)) { bv = ov; ba = oa; }
        }
        if (cpart == 0) {
            int gcol = (int)r * NCOL + ccol;
            if (gcol == 0) bv = P[0] + LT00;              // j==0 VALUE override
            float nv = bv + e;
#pragma unroll
            for (int rr = 0; rr < CSZ; rr++)
                rp[rr][bw * NST + gcol] = nv;             // broadcast to all mirrors
            g_bp[step * NST + gcol] = (unsigned short)ba;
        }
        cluster.sync();                                   // publishes spf[bw] everywhere
    }

    // ---- final-column first-max argmax (CTA 0 only; final column in spf[0]) ----
    if (r == 0) {
        const float* F = spf[((TT - 1) & 1) ^ 1];
        float v = F[2 * t]; int idx = 2 * t;
        if (F[2 * t + 1] > v) { v = F[2 * t + 1]; idx = 2 * t + 1; }
        for (int o = 16; o; o >>= 1) {
            float ov = __shfl_xor_sync(FULL, v, o);
            int   oi = __shfl_xor_sync(FULL, idx, o);
            if (ov > v || (ov == v && oi < idx)) { v = ov; idx = oi; }
        }
        if (lane == 0) { s_rv[wid] = v; s_ri[wid] = idx; }
        __syncthreads();
        if (t == 0) {
            for (int w = 1; w < NGRP; w++)
                if (s_rv[w] > v || (s_rv[w] == v && s_ri[w] < idx)) { v = s_rv[w]; idx = s_ri[w]; }
            g_last = idx;
        }
    }
}

// ---------------- K4a: fill ENTIRE output buffer with `last` (float) ----------------
__global__ void k_fill(float* __restrict__ out, int n) {
    int last = g_last;
    for (int i = blockIdx.x * 256 + threadIdx.x; i < n; i += gridDim.x * 256)
        out[i] = (float)last;
}

// ---------------- K4b: serial backtrack, FLOAT output ----------------
// sequence = [s_0 .. s_{T-2}, last, last]
__global__ void k_backtrack(float* __restrict__ out) {
    int cur = g_last;
    out[TT] = (float)cur;
    out[TT - 1] = (float)cur;
    for (int i = TT - 2; i >= 0; i--) {
        cur = (int)g_bp[(i + 1) * NST + cur];
        out[i] = (float)cur;
    }
}

// ---------------- launch ----------------
extern "C" void kernel_launch(void* const* d_in, const int* in_sizes, int n_in,
                              void* d_out, int out_size) {
    // Bind inputs BY ELEMENT COUNT (all four counts distinct):
    //   evidence [T,D]=81920, prior [N]=1024, trans [N,N]=1048576, emission [N,D,2]=40960
    const float* evidence = 0;
    const float* prior = 0;
    const float* trans = 0;
    const float* emis = 0;
    for (int i = 0; i < n_in; i++) {
        switch (in_sizes[i]) {
            case TT * DD:       evidence = (const float*)d_in[i]; break;
            case NST:           prior    = (const float*)d_in[i]; break;
            case NST * NST:     trans    = (const float*)d_in[i]; break;
            case NST * DD * 2:  emis     = (const float*)d_in[i]; break;
        }
    }
    float* out = (float*)d_out;

    k_lt<<<NST, 256>>>(trans);
    k_params<<<NST, 32>>>(emis);
    k_emis<<<dim3(TT / 64, NST / 256), 256>>>(evidence);
    k_viterbi<<<CSZ, CTHR>>>(prior);
    int n = out_size > 0 ? out_size : (TT + 1);
    int g = (n + 255) / 256; if (g > 64) g = 64;
    k_fill<<<g, 256>>>(out, n);
    k_backtrack<<<1, 1>>>(out);
}